// round 15
// baseline (speedup 1.0000x reference)
#include <cuda_runtime.h>
#include <cuda_bf16.h>
#include <math.h>

#define BB    2048
#define U1N   101
#define DN    128
#define STEPN 165
#define HN    200
#define IM1   63
#define NPAD  224          // padded N: 28 n8-tiles
#define LDA   136          // padded A leading dim (bf16): conflict-free ldmatrix
#define NT8   28
#define KS    8            // k16 steps

// ---------------------------------------------------------------------------
// B pre-packed in mma.sync m16n8k16 register layout (see bpack_kernel)
__device__ uint4 g_Bpk[NT8 * KS * 32];
// transposed weight tables for streaming matvecs
__device__ float g_W1T[HN * 384];      // [o][k], k-bands: rows 2+k / 130+k
__device__ float g_WscT[128 * 256];    // [d][k]
__device__ float g_bias[HN];           // b1[o] + 0.5*W1[1][o]
__device__ int g_mask_is_i32;

// ---------------------------------------------------------------------------
__global__ void flag_init_kernel() { g_mask_is_i32 = 1; }

__global__ __launch_bounds__(256) void mask_detect_kernel(const unsigned* __restrict__ m)
{
    int n = (BB * U1N) / 4;
    for (int idx = blockIdx.x * 256 + threadIdx.x; idx < n; idx += gridDim.x * 256) {
        if (m[idx] > 1u) { atomicExch(&g_mask_is_i32, 0); return; }
    }
}

__global__ __launch_bounds__(256) void bpack_kernel(const float* __restrict__ W1)
{
    int t = blockIdx.x * 256 + threadIdx.x;
    if (t >= NT8 * KS * 32) return;
    int lane = t & 31, ks = (t >> 5) & 7, jt = t >> 8;
    int n  = jt * 8 + (lane >> 2);
    int k0 = ks * 16 + (lane & 3) * 2;
    float v[4];
    int kk[4] = { k0, k0 + 1, k0 + 8, k0 + 9 };
    #pragma unroll
    for (int i = 0; i < 4; ++i)
        v[i] = (n < HN) ? W1[(size_t)(130 + kk[i]) * HN + n] : 0.f;
    __nv_bfloat16 h[4]; float l[4];
    #pragma unroll
    for (int i = 0; i < 4; ++i) {
        h[i] = __float2bfloat16_rn(v[i]);
        l[i] = v[i] - __bfloat162float(h[i]);
    }
    __nv_bfloat162 bh0 = __halves2bfloat162(h[0], h[1]);
    __nv_bfloat162 bh1 = __halves2bfloat162(h[2], h[3]);
    __nv_bfloat162 bl0 = __floats2bfloat162_rn(l[0], l[1]);
    __nv_bfloat162 bl1 = __floats2bfloat162_rn(l[2], l[3]);
    uint4 r;
    r.x = *(unsigned*)&bh0; r.y = *(unsigned*)&bh1;
    r.z = *(unsigned*)&bl0; r.w = *(unsigned*)&bl1;
    g_Bpk[t] = r;
}

// pack g_W1T / g_WscT / g_bias
__global__ __launch_bounds__(256) void wpack_kernel(
    const float* __restrict__ W1, const float* __restrict__ W_sc,
    const float* __restrict__ b1)
{
    int idx = blockIdx.x * 256 + threadIdx.x;
    const int n1 = HN * 384;
    const int n2 = 128 * 256;
    if (idx < n1) {
        int o = idx / 384, k = idx % 384;
        int row = (k < 128) ? (2 + k) : (130 + k);   // 258+(k-128) = 386+(k-256) = 130+k
        g_W1T[idx] = W1[(size_t)row * HN + o];
    } else if (idx < n1 + n2) {
        int j = idx - n1;
        int d = j / 256, k = j % 256;
        g_WscT[j] = W_sc[(size_t)k * 128 + d];
    } else if (idx < n1 + n2 + HN) {
        int o = idx - n1 - n2;
        g_bias[o] = b1[o] + 0.5f * W1[HN + o];       // idx feature = 64/128 = 0.5
    }
}

// ---------------------------------------------------------------------------
__device__ __forceinline__ unsigned smem_u32(const void* p) {
    unsigned a;
    asm("{ .reg .u64 t; cvta.to.shared.u64 t, %1; cvt.u32.u64 %0, t; }"
        : "=r"(a) : "l"(p));
    return a;
}
#define LDSM4(r0, r1, r2, r3, addr) \
    asm volatile("ldmatrix.sync.aligned.m8n8.x4.shared.b16 {%0,%1,%2,%3}, [%4];" \
        : "=r"(r0), "=r"(r1), "=r"(r2), "=r"(r3) : "r"(addr))
#define MMA16816(c, a0, a1, a2, a3, b0, b1) \
    asm volatile("mma.sync.aligned.m16n8k16.row.col.f32.bf16.bf16.f32 " \
        "{%0,%1,%2,%3}, {%4,%5,%6,%7}, {%8,%9}, {%0,%1,%2,%3};" \
        : "+f"((c)[0]), "+f"((c)[1]), "+f"((c)[2]), "+f"((c)[3]) \
        : "r"(a0), "r"(a1), "r"(a2), "r"(a3), "r"(b0), "r"(b1))

// ---------------------------------------------------------------------------
// dynamic smem layout (per CTA ~90 KB -> 2 CTAs/SM):
static const int OFF_AH   = 0;
static const int OFF_AL   = 34816;
static const int OFF_PART = 69632;     // 3 x 8 x 32 float4 = 12288
static const int OFF_TAIL = 81920;

struct Tail {
    float s_minc[128];
    float s_v2[256];        // [msel | mhist]
    float s_v[384];         // [minc | sc | memb]
    float s_base[224], s_w1r0[224], s_w2[224];
    float s_w[128];
    float s_red[2][128];
    float s_pi[128];
    float s_lse;
    int   s_sel_idx;
};

// ---------------------------------------------------------------------------
__global__ __launch_bounds__(256, 2) void fused_kernel(
    const float* __restrict__ emb, const float* __restrict__ w,
    const float* __restrict__ b_sc, const float* __restrict__ W1,
    const float* __restrict__ W2, const float* __restrict__ b2,
    const int* __restrict__ seq, const void* __restrict__ mask,
    float* __restrict__ out, int mode)
{
    extern __shared__ char smem[];
    Tail* T = (Tail*)(smem + OFF_TAIL);
    __nv_bfloat16* A_hi = (__nv_bfloat16*)(smem + OFF_AH);
    __nv_bfloat16* A_lo = (__nv_bfloat16*)(smem + OFF_AL);
    float4* part = (float4*)(smem + OFF_PART);       // [3][8][32]

    int b    = blockIdx.x;
    int tid  = threadIdx.x;
    int lane = tid & 31;
    int wid  = tid >> 5;                             // 0..7

    // ---- phase 0: small loads ----
    if (tid < 224) {
        T->s_w1r0[tid] = (tid < HN) ? W1[tid] : 0.f;
        T->s_w2[tid]   = (tid < HN) ? W2[tid] : 0.f;
    }
    if (tid < 128) T->s_w[tid] = (tid < U1N) ? w[b * U1N + tid] : 0.f;

    // ---- phase 1: emb pass (means + A hi/lo bf16 staging) + gather ----
    {
        int q = tid & 31;          // float4 column (k = 4q..4q+3)
        int h = tid >> 5;          // 0..7
        const float4* eb4 = (const float4*)(emb + (size_t)b * STEPN * DN);
        const float4* e4  = (const float4*)emb;

        float4 se = make_float4(0.f, 0.f, 0.f, 0.f);
        float4 sh = se, ss = se;
        #pragma unroll 4
        for (int r = h; r < STEPN; r += 8) {
            float4 v = eb4[r * 32 + q];
            se.x += v.x; se.y += v.y; se.z += v.z; se.w += v.w;
            if (r >= 101 && r < 164) {
                sh.x += v.x; sh.y += v.y; sh.z += v.z; sh.w += v.w;
            }
            if (r == 164) ((float4*)T->s_minc)[q] = v;
            if (r < 128) {
                __nv_bfloat162 h01 = __floats2bfloat162_rn(v.x, v.y);
                __nv_bfloat162 h23 = __floats2bfloat162_rn(v.z, v.w);
                float lx = v.x - __bfloat162float(__low2bfloat16(h01));
                float ly = v.y - __bfloat162float(__high2bfloat16(h01));
                float lz = v.z - __bfloat162float(__low2bfloat16(h23));
                float lw = v.w - __bfloat162float(__high2bfloat16(h23));
                __nv_bfloat162 l01 = __floats2bfloat162_rn(lx, ly);
                __nv_bfloat162 l23 = __floats2bfloat162_rn(lz, lw);
                unsigned* dh = (unsigned*)&A_hi[r * LDA + 4 * q];
                unsigned* dl = (unsigned*)&A_lo[r * LDA + 4 * q];
                dh[0] = *(unsigned*)&h01; dh[1] = *(unsigned*)&h23;
                dl[0] = *(unsigned*)&l01; dl[1] = *(unsigned*)&l23;
            }
        }
        #pragma unroll 4
        for (int j = h; j < IM1; j += 8) {
            int s = seq[b * IM1 + j];
            float4 v = e4[((size_t)b * IM1 + s) * 32 + q];  // deliberate cross-batch gather
            ss.x += v.x; ss.y += v.y; ss.z += v.z; ss.w += v.w;
        }
        part[0 * 256 + h * 32 + q] = se;
        part[1 * 256 + h * 32 + q] = sh;
        part[2 * 256 + h * 32 + q] = ss;
    }
    __syncthreads();

    // ---- phase 2: combine means; fill v2 and v ----
    if (tid < 128) {
        int d = tid;
        const float* pe = (const float*)&part[0];
        const float* ph = (const float*)&part[256];
        const float* ps = (const float*)&part[512];
        float ae = 0.f, ah = 0.f, as = 0.f;
        #pragma unroll
        for (int g = 0; g < 8; ++g) {
            ae += pe[g * 128 + d]; ah += ph[g * 128 + d]; as += ps[g * 128 + d];
        }
        T->s_v2[d]       = as * (1.f / IM1);     // msel
        T->s_v2[128 + d] = ah * (1.f / IM1);     // mhist
        T->s_v[d]        = T->s_minc[d];         // minc
        T->s_v[256 + d]  = ae * (1.f / STEPN);   // memb
    }
    __syncthreads();

    // ---- phase 3: step_context via transposed streaming ----
    if (tid < 128) {
        const float4* wr = (const float4*)(g_WscT + (size_t)tid * 256);
        const float4* vv = (const float4*)T->s_v2;
        float4 a0 = make_float4(0.f, 0.f, 0.f, 0.f), a1 = a0;
        #pragma unroll 8
        for (int i = 0; i < 64; i += 2) {
            float4 w0 = wr[i],     x0 = vv[i];
            float4 w1v = wr[i + 1], x1 = vv[i + 1];
            a0.x = fmaf(w0.x, x0.x, a0.x); a0.y = fmaf(w0.y, x0.y, a0.y);
            a0.z = fmaf(w0.z, x0.z, a0.z); a0.w = fmaf(w0.w, x0.w, a0.w);
            a1.x = fmaf(w1v.x, x1.x, a1.x); a1.y = fmaf(w1v.y, x1.y, a1.y);
            a1.z = fmaf(w1v.z, x1.z, a1.z); a1.w = fmaf(w1v.w, x1.w, a1.w);
        }
        T->s_v[128 + tid] = a0.x + a0.y + a0.z + a0.w
                          + a1.x + a1.y + a1.z + a1.w + b_sc[tid];
    }
    __syncthreads();

    // ---- phase 4: base[o] via transposed streaming ----
    if (tid < 224) {
        float bv = 0.f;
        if (tid < HN) {
            const float4* wr = (const float4*)(g_W1T + (size_t)tid * 384);
            const float4* vv = (const float4*)T->s_v;
            float4 a0 = make_float4(0.f, 0.f, 0.f, 0.f), a1 = a0;
            #pragma unroll 8
            for (int i = 0; i < 96; i += 2) {
                float4 w0 = wr[i],      x0 = vv[i];
                float4 w1v = wr[i + 1], x1 = vv[i + 1];
                a0.x = fmaf(w0.x, x0.x, a0.x); a0.y = fmaf(w0.y, x0.y, a0.y);
                a0.z = fmaf(w0.z, x0.z, a0.z); a0.w = fmaf(w0.w, x0.w, a0.w);
                a1.x = fmaf(w1v.x, x1.x, a1.x); a1.y = fmaf(w1v.y, x1.y, a1.y);
                a1.z = fmaf(w1v.z, x1.z, a1.z); a1.w = fmaf(w1v.w, x1.w, a1.w);
            }
            bv = a0.x + a0.y + a0.z + a0.w + a1.x + a1.y + a1.z + a1.w
               + g_bias[tid];
        }
        T->s_base[tid] = bv;
    }
    __syncthreads();

    // ---- GEMM + fused epilogue: 8 warps x 1 m-tile, n-groups sequential ----
    {
        int mtile = wid;
        int gid   = lane >> 2, tig = lane & 3;
        int arow  = mtile * 16 + (lane & 7) + ((lane >> 3) & 1) * 8;
        int acolh = (lane >> 4) * 8;
        unsigned ah_addr = smem_u32(A_hi) + (arow * LDA + acolh) * 2;
        unsigned al_addr = smem_u32(A_lo) + (arow * LDA + acolh) * 2;
        float wu0 = T->s_w[mtile * 16 + gid];
        float wu1 = T->s_w[mtile * 16 + gid + 8];

        #pragma unroll 1
        for (int ngrp = 0; ngrp < 2; ++ngrp) {
            float acc[14][4];
            #pragma unroll
            for (int jt = 0; jt < 14; ++jt)
                #pragma unroll
                for (int i = 0; i < 4; ++i) acc[jt][i] = 0.f;

            const uint4* bp = g_Bpk + (size_t)(ngrp * 14) * KS * 32 + lane;
            #pragma unroll 1
            for (int ks = 0; ks < KS; ++ks) {
                unsigned ah0, ah1, ah2, ah3, al0, al1, al2, al3;
                LDSM4(ah0, ah1, ah2, ah3, ah_addr + ks * 32);
                LDSM4(al0, al1, al2, al3, al_addr + ks * 32);
                #pragma unroll
                for (int jt = 0; jt < 14; ++jt) {
                    uint4 bv = bp[(jt * KS + ks) * 32];
                    MMA16816(acc[jt], ah0, ah1, ah2, ah3, bv.x, bv.y);
                    MMA16816(acc[jt], al0, al1, al2, al3, bv.x, bv.y);
                    MMA16816(acc[jt], ah0, ah1, ah2, ah3, bv.z, bv.w);
                }
            }

            float sum0 = 0.f, sum1 = 0.f;
            #pragma unroll
            for (int jt = 0; jt < 14; ++jt) {
                int c = ngrp * 112 + jt * 8 + tig * 2;
                float2 bs  = *(const float2*)&T->s_base[c];
                float2 w1r = *(const float2*)&T->s_w1r0[c];
                float2 w2v = *(const float2*)&T->s_w2[c];
                sum0 += fmaxf(acc[jt][0] + bs.x + wu0 * w1r.x, 0.f) * w2v.x;
                sum0 += fmaxf(acc[jt][1] + bs.y + wu0 * w1r.y, 0.f) * w2v.y;
                sum1 += fmaxf(acc[jt][2] + bs.x + wu1 * w1r.x, 0.f) * w2v.x;
                sum1 += fmaxf(acc[jt][3] + bs.y + wu1 * w1r.y, 0.f) * w2v.y;
            }
            sum0 += __shfl_xor_sync(0xffffffffu, sum0, 1);
            sum0 += __shfl_xor_sync(0xffffffffu, sum0, 2);
            sum1 += __shfl_xor_sync(0xffffffffu, sum1, 1);
            sum1 += __shfl_xor_sync(0xffffffffu, sum1, 2);
            if (tig == 0) {
                T->s_red[ngrp][mtile * 16 + gid]     = sum0;
                T->s_red[ngrp][mtile * 16 + gid + 8] = sum1;
            }
        }
    }
    __syncthreads();

    // ---- pi combine + mask (dtype-adaptive) ----
    float bb2 = b2[0];
    if (tid < U1N) {
        bool mv;
        if (g_mask_is_i32)
            mv = ((const int*)mask)[b * U1N + tid] != 0;
        else
            mv = ((const unsigned char*)mask)[b * U1N + tid] != 0;
        float pv = bb2 + T->s_red[0][tid] + T->s_red[1][tid];
        T->s_pi[tid] = mv ? -1000000.0f : pv;
    }
    __syncthreads();

    // ---- log_softmax + argmax (warp 0) ----
    if (wid == 0) {
        float mv = -3.4e38f; int mi = U1N;
        for (int u = lane; u < U1N; u += 32) {
            float v = T->s_pi[u];
            if (v > mv) { mv = v; mi = u; }
        }
        #pragma unroll
        for (int off = 16; off; off >>= 1) {
            float ov = __shfl_xor_sync(0xffffffffu, mv, off);
            int   oi = __shfl_xor_sync(0xffffffffu, mi, off);
            if (ov > mv || (ov == mv && oi < mi)) { mv = ov; mi = oi; }
        }
        float se = 0.f;
        for (int u = lane; u < U1N; u += 32) se += expf(T->s_pi[u] - mv);
        #pragma unroll
        for (int off = 16; off; off >>= 1)
            se += __shfl_xor_sync(0xffffffffu, se, off);
        if (lane == 0) { T->s_lse = mv + logf(se); T->s_sel_idx = mi; }
    }
    __syncthreads();

    float lse = T->s_lse;
    if (mode == 0) {
        for (int u = tid; u < U1N; u += 256)
            out[b * U1N + u] = T->s_pi[u] - lse;
    } else if (mode == 1) {
        if (tid == 0) out[b] = (float)T->s_sel_idx;
        float* op = out + BB;
        for (int u = tid; u < U1N; u += 256)
            op[b * U1N + u] = T->s_pi[u] - lse;
    } else {
        if (tid == 0) ((int*)out)[b] = T->s_sel_idx;
    }
}

// ---------------------------------------------------------------------------
extern "C" void kernel_launch(void* const* d_in, const int* in_sizes, int n_in,
                              void* d_out, int out_size)
{
    const float* emb  = (const float*)d_in[0];
    const float* w    = (const float*)d_in[1];
    const float* W_sc = (const float*)d_in[2];
    const float* b_sc = (const float*)d_in[3];
    const float* W1   = (const float*)d_in[4];
    const float* b1   = (const float*)d_in[5];
    const float* W2   = (const float*)d_in[6];
    const float* b2   = (const float*)d_in[7];
    const int*   seq  = (const int*)d_in[8];
    const void*  mask = d_in[9];

    int mode = 1;
    if (out_size == BB * U1N) mode = 0;
    else if (out_size == BB)  mode = 2;

    static int smem_sz = 0;
    if (!smem_sz) {
        smem_sz = OFF_TAIL + (int)sizeof(Tail);
        cudaFuncSetAttribute(fused_kernel,
                             cudaFuncAttributeMaxDynamicSharedMemorySize, smem_sz);
    }

    flag_init_kernel<<<1, 1>>>();
    mask_detect_kernel<<<208, 256>>>((const unsigned*)mask);
    bpack_kernel<<<(NT8 * KS * 32 + 255) / 256, 256>>>(W1);
    wpack_kernel<<<(HN * 384 + 128 * 256 + HN + 255) / 256, 256>>>(W1, W_sc, b1);
    fused_kernel<<<BB, 256, smem_sz>>>(emb, w, b_sc, W1, W2, b2,
                                       seq, mask, (float*)d_out, mode);
}

// round 16
// speedup vs baseline: 1.7243x; 1.7243x over previous
#include <cuda_runtime.h>
#include <cuda_bf16.h>
#include <math.h>

#define BB    2048
#define U1N   101
#define DN    128
#define STEPN 165
#define HN    200
#define IM1   63
#define NPAD  224          // padded N: 28 n8-tiles
#define LDA   136          // padded A leading dim (bf16): conflict-free ldmatrix
#define NT8   28
#define KS    8            // k16 steps

// ---------------------------------------------------------------------------
// B pre-packed in mma.sync m16n8k16 register layout (see bpack_kernel)
__device__ uint4 g_Bpk[NT8 * KS * 32];
__device__ int g_mask_is_i32;

// ---------------------------------------------------------------------------
__global__ void flag_init_kernel() { g_mask_is_i32 = 1; }

__global__ __launch_bounds__(256) void mask_detect_kernel(const unsigned* __restrict__ m)
{
    int n = (BB * U1N) / 4;
    for (int idx = blockIdx.x * 256 + threadIdx.x; idx < n; idx += gridDim.x * 256) {
        if (m[idx] > 1u) { atomicExch(&g_mask_is_i32, 0); return; }
    }
}

__global__ __launch_bounds__(256) void bpack_kernel(const float* __restrict__ W1)
{
    int t = blockIdx.x * 256 + threadIdx.x;
    if (t >= NT8 * KS * 32) return;
    int lane = t & 31, ks = (t >> 5) & 7, jt = t >> 8;
    int n  = jt * 8 + (lane >> 2);
    int k0 = ks * 16 + (lane & 3) * 2;
    float v[4];
    int kk[4] = { k0, k0 + 1, k0 + 8, k0 + 9 };
    #pragma unroll
    for (int i = 0; i < 4; ++i)
        v[i] = (n < HN) ? W1[(size_t)(130 + kk[i]) * HN + n] : 0.f;
    __nv_bfloat16 h[4]; float l[4];
    #pragma unroll
    for (int i = 0; i < 4; ++i) {
        h[i] = __float2bfloat16_rn(v[i]);
        l[i] = v[i] - __bfloat162float(h[i]);
    }
    __nv_bfloat162 bh0 = __halves2bfloat162(h[0], h[1]);
    __nv_bfloat162 bh1 = __halves2bfloat162(h[2], h[3]);
    __nv_bfloat162 bl0 = __floats2bfloat162_rn(l[0], l[1]);
    __nv_bfloat162 bl1 = __floats2bfloat162_rn(l[2], l[3]);
    uint4 r;
    r.x = *(unsigned*)&bh0; r.y = *(unsigned*)&bh1;
    r.z = *(unsigned*)&bl0; r.w = *(unsigned*)&bl1;
    g_Bpk[t] = r;
}

// ---------------------------------------------------------------------------
__device__ __forceinline__ unsigned smem_u32(const void* p) {
    unsigned a;
    asm("{ .reg .u64 t; cvta.to.shared.u64 t, %1; cvt.u32.u64 %0, t; }"
        : "=r"(a) : "l"(p));
    return a;
}
#define LDSM4(r0, r1, r2, r3, addr) \
    asm volatile("ldmatrix.sync.aligned.m8n8.x4.shared.b16 {%0,%1,%2,%3}, [%4];" \
        : "=r"(r0), "=r"(r1), "=r"(r2), "=r"(r3) : "r"(addr))
#define MMA16816(c, a0, a1, a2, a3, b0, b1) \
    asm volatile("mma.sync.aligned.m16n8k16.row.col.f32.bf16.bf16.f32 " \
        "{%0,%1,%2,%3}, {%4,%5,%6,%7}, {%8,%9}, {%0,%1,%2,%3};" \
        : "+f"((c)[0]), "+f"((c)[1]), "+f"((c)[2]), "+f"((c)[3]) \
        : "r"(a0), "r"(a1), "r"(a2), "r"(a3), "r"(b0), "r"(b1))

// ---------------------------------------------------------------------------
// dynamic smem layout (per CTA ~91 KB -> 2 CTAs/SM):
static const int OFF_AH   = 0;
static const int OFF_AL   = 34816;
static const int OFF_PART = 69632;     // 3 x 8 x 32 float4 = 12288
static const int OFF_TAIL = 81920;

struct Tail {
    float s_minc[128], s_memb[128], s_mhist[128], s_msel[128], s_sc[128];
    float s_scp[2][128];
    float s_base[224], s_w1r0[224], s_w2[224];
    float s_w[128];
    float s_red[2][128];
    float s_pi[128];
    int   s_seq[64];
    float s_lse;
    int   s_sel_idx;
};

// ---------------------------------------------------------------------------
__global__ __launch_bounds__(256, 2) void fused_kernel(
    const float* __restrict__ emb, const float* __restrict__ w,
    const float* __restrict__ W_sc, const float* __restrict__ b_sc,
    const float* __restrict__ W1, const float* __restrict__ b1,
    const float* __restrict__ W2, const float* __restrict__ b2,
    const int* __restrict__ seq, const void* __restrict__ mask,
    float* __restrict__ out, int mode)
{
    extern __shared__ char smem[];
    Tail* T = (Tail*)(smem + OFF_TAIL);
    __nv_bfloat16* A_hi = (__nv_bfloat16*)(smem + OFF_AH);
    __nv_bfloat16* A_lo = (__nv_bfloat16*)(smem + OFF_AL);
    float4* part = (float4*)(smem + OFF_PART);       // [3][8][32]

    int b    = blockIdx.x;
    int tid  = threadIdx.x;
    int lane = tid & 31;
    int wid  = tid >> 5;                             // 0..7

    // ---- phase 0: small loads + seq preload ----
    if (tid < 224) {
        T->s_w1r0[tid] = (tid < HN) ? W1[tid] : 0.f;
        T->s_w2[tid]   = (tid < HN) ? W2[tid] : 0.f;
    }
    if (tid < 128) T->s_w[tid] = (tid < U1N) ? w[b * U1N + tid] : 0.f;
    if (tid >= 128 && tid < 128 + IM1) T->s_seq[tid - 128] = seq[b * IM1 + (tid - 128)];
    __syncthreads();

    // ---- phase 1: emb pass (branch-free loop split) + gather ----
    {
        int q = tid & 31;          // float4 column (k = 4q..4q+3)
        int h = tid >> 5;          // 0..7
        const float4* eb4 = (const float4*)(emb + (size_t)b * STEPN * DN);
        const float4* e4  = (const float4*)emb;

        float4 se = make_float4(0.f, 0.f, 0.f, 0.f);
        float4 sh = se, ss = se;

        // rows [0,101): sum + A-stage
        #pragma unroll 4
        for (int r = h; r < 101; r += 8) {
            float4 v = eb4[r * 32 + q];
            se.x += v.x; se.y += v.y; se.z += v.z; se.w += v.w;
            __nv_bfloat162 h01 = __floats2bfloat162_rn(v.x, v.y);
            __nv_bfloat162 h23 = __floats2bfloat162_rn(v.z, v.w);
            float lx = v.x - __bfloat162float(__low2bfloat16(h01));
            float ly = v.y - __bfloat162float(__high2bfloat16(h01));
            float lz = v.z - __bfloat162float(__low2bfloat16(h23));
            float lw = v.w - __bfloat162float(__high2bfloat16(h23));
            __nv_bfloat162 l01 = __floats2bfloat162_rn(lx, ly);
            __nv_bfloat162 l23 = __floats2bfloat162_rn(lz, lw);
            unsigned* dh = (unsigned*)&A_hi[r * LDA + 4 * q];
            unsigned* dl = (unsigned*)&A_lo[r * LDA + 4 * q];
            dh[0] = *(unsigned*)&h01; dh[1] = *(unsigned*)&h23;
            dl[0] = *(unsigned*)&l01; dl[1] = *(unsigned*)&l23;
        }
        // rows [101,128): sum + hist + A-stage
        int r2 = h + (((101 - h) + 7) >> 3) * 8;
        #pragma unroll 2
        for (int r = r2; r < 128; r += 8) {
            float4 v = eb4[r * 32 + q];
            se.x += v.x; se.y += v.y; se.z += v.z; se.w += v.w;
            sh.x += v.x; sh.y += v.y; sh.z += v.z; sh.w += v.w;
            __nv_bfloat162 h01 = __floats2bfloat162_rn(v.x, v.y);
            __nv_bfloat162 h23 = __floats2bfloat162_rn(v.z, v.w);
            float lx = v.x - __bfloat162float(__low2bfloat16(h01));
            float ly = v.y - __bfloat162float(__high2bfloat16(h01));
            float lz = v.z - __bfloat162float(__low2bfloat16(h23));
            float lw = v.w - __bfloat162float(__high2bfloat16(h23));
            __nv_bfloat162 l01 = __floats2bfloat162_rn(lx, ly);
            __nv_bfloat162 l23 = __floats2bfloat162_rn(lz, lw);
            unsigned* dh = (unsigned*)&A_hi[r * LDA + 4 * q];
            unsigned* dl = (unsigned*)&A_lo[r * LDA + 4 * q];
            dh[0] = *(unsigned*)&h01; dh[1] = *(unsigned*)&h23;
            dl[0] = *(unsigned*)&l01; dl[1] = *(unsigned*)&l23;
        }
        // rows [128,164): sum + hist
        int r3 = h + (((128 - h) + 7) >> 3) * 8;
        #pragma unroll 4
        for (int r = r3; r < 164; r += 8) {
            float4 v = eb4[r * 32 + q];
            se.x += v.x; se.y += v.y; se.z += v.z; se.w += v.w;
            sh.x += v.x; sh.y += v.y; sh.z += v.z; sh.w += v.w;
        }
        // row 164 (h == 164 % 8 == 4): sum + minc
        if (h == 4) {
            float4 v = eb4[164 * 32 + q];
            se.x += v.x; se.y += v.y; se.z += v.z; se.w += v.w;
            ((float4*)T->s_minc)[q] = v;
        }
        // gather (seq from smem; 8 independent loads)
        #pragma unroll 8
        for (int j = h; j < IM1; j += 8) {
            int s = T->s_seq[j];
            float4 v = e4[((size_t)b * IM1 + s) * 32 + q];  // deliberate cross-batch gather
            ss.x += v.x; ss.y += v.y; ss.z += v.z; ss.w += v.w;
        }
        part[0 * 256 + h * 32 + q] = se;
        part[1 * 256 + h * 32 + q] = sh;
        part[2 * 256 + h * 32 + q] = ss;
    }
    __syncthreads();

    // ---- phase 2: combine means ----
    if (tid < 128) {
        int d = tid;
        const float* pe = (const float*)&part[0];
        const float* ph = (const float*)&part[256];
        const float* ps = (const float*)&part[512];
        float ae = 0.f, ah = 0.f, as = 0.f;
        #pragma unroll
        for (int g = 0; g < 8; ++g) {
            ae += pe[g * 128 + d]; ah += ph[g * 128 + d]; as += ps[g * 128 + d];
        }
        T->s_memb[d]  = ae * (1.f / STEPN);
        T->s_mhist[d] = ah * (1.f / IM1);
        T->s_msel[d]  = as * (1.f / IM1);
    }
    __syncthreads();

    // ---- phase 3: step_context (coalesced over d, 4 acc chains) ----
    {
        int g = tid >> 7, d = tid & 127;
        const float* vsrc = g ? T->s_mhist : T->s_msel;
        const float* wsrc = W_sc + (size_t)(g ? 128 : 0) * 128;
        float a0 = 0.f, a1 = 0.f, a2 = 0.f, a3 = 0.f;
        #pragma unroll 8
        for (int k = 0; k < 128; k += 4) {
            a0 = fmaf(vsrc[k],     wsrc[(k)     * 128 + d], a0);
            a1 = fmaf(vsrc[k + 1], wsrc[(k + 1) * 128 + d], a1);
            a2 = fmaf(vsrc[k + 2], wsrc[(k + 2) * 128 + d], a2);
            a3 = fmaf(vsrc[k + 3], wsrc[(k + 3) * 128 + d], a3);
        }
        T->s_scp[g][d] = (a0 + a1) + (a2 + a3);
    }
    __syncthreads();
    if (tid < 128) T->s_sc[tid] = T->s_scp[0][tid] + T->s_scp[1][tid] + b_sc[tid];
    __syncthreads();

    // ---- phase 4: base[o] (coalesced over o, 4 acc chains per band) ----
    if (tid < 224) {
        int o = tid;
        float bv = 0.f;
        if (o < HN) {
            float a0 = b1[o] + 0.5f * W1[HN + o];   // idx feature = 64/128 = 0.5
            float a1 = 0.f, a2 = 0.f, a3 = 0.f;
            #pragma unroll 8
            for (int k = 0; k < 128; k += 4) {
                a0 = fmaf(T->s_minc[k],     W1[(size_t)(2 + k) * HN + o], a0);
                a1 = fmaf(T->s_minc[k + 1], W1[(size_t)(3 + k) * HN + o], a1);
                a2 = fmaf(T->s_minc[k + 2], W1[(size_t)(4 + k) * HN + o], a2);
                a3 = fmaf(T->s_minc[k + 3], W1[(size_t)(5 + k) * HN + o], a3);
            }
            #pragma unroll 8
            for (int k = 0; k < 128; k += 4) {
                a0 = fmaf(T->s_sc[k],     W1[(size_t)(258 + k) * HN + o], a0);
                a1 = fmaf(T->s_sc[k + 1], W1[(size_t)(259 + k) * HN + o], a1);
                a2 = fmaf(T->s_sc[k + 2], W1[(size_t)(260 + k) * HN + o], a2);
                a3 = fmaf(T->s_sc[k + 3], W1[(size_t)(261 + k) * HN + o], a3);
            }
            #pragma unroll 8
            for (int k = 0; k < 128; k += 4) {
                a0 = fmaf(T->s_memb[k],     W1[(size_t)(386 + k) * HN + o], a0);
                a1 = fmaf(T->s_memb[k + 1], W1[(size_t)(387 + k) * HN + o], a1);
                a2 = fmaf(T->s_memb[k + 2], W1[(size_t)(388 + k) * HN + o], a2);
                a3 = fmaf(T->s_memb[k + 3], W1[(size_t)(389 + k) * HN + o], a3);
            }
            bv = (a0 + a1) + (a2 + a3);
        }
        T->s_base[o] = bv;
    }
    __syncthreads();

    // ---- GEMM + fused epilogue: 8 warps x 1 m-tile, n-groups sequential ----
    {
        int mtile = wid;
        int gid   = lane >> 2, tig = lane & 3;
        int arow  = mtile * 16 + (lane & 7) + ((lane >> 3) & 1) * 8;
        int acolh = (lane >> 4) * 8;
        unsigned ah_addr = smem_u32(A_hi) + (arow * LDA + acolh) * 2;
        unsigned al_addr = smem_u32(A_lo) + (arow * LDA + acolh) * 2;
        float wu0 = T->s_w[mtile * 16 + gid];
        float wu1 = T->s_w[mtile * 16 + gid + 8];

        #pragma unroll 1
        for (int ngrp = 0; ngrp < 2; ++ngrp) {
            float acc[14][4];
            #pragma unroll
            for (int jt = 0; jt < 14; ++jt)
                #pragma unroll
                for (int i = 0; i < 4; ++i) acc[jt][i] = 0.f;

            const uint4* bp = g_Bpk + (size_t)(ngrp * 14) * KS * 32 + lane;
            #pragma unroll 1
            for (int ks = 0; ks < KS; ++ks) {
                unsigned ah0, ah1, ah2, ah3, al0, al1, al2, al3;
                LDSM4(ah0, ah1, ah2, ah3, ah_addr + ks * 32);
                LDSM4(al0, al1, al2, al3, al_addr + ks * 32);
                #pragma unroll
                for (int jt = 0; jt < 14; ++jt) {
                    uint4 bv = bp[(jt * KS + ks) * 32];
                    MMA16816(acc[jt], ah0, ah1, ah2, ah3, bv.x, bv.y);
                    MMA16816(acc[jt], al0, al1, al2, al3, bv.x, bv.y);
                    MMA16816(acc[jt], ah0, ah1, ah2, ah3, bv.z, bv.w);
                }
            }

            float sum0 = 0.f, sum1 = 0.f;
            #pragma unroll
            for (int jt = 0; jt < 14; ++jt) {
                int c = ngrp * 112 + jt * 8 + tig * 2;
                float2 bs  = *(const float2*)&T->s_base[c];
                float2 w1r = *(const float2*)&T->s_w1r0[c];
                float2 w2v = *(const float2*)&T->s_w2[c];
                sum0 += fmaxf(acc[jt][0] + bs.x + wu0 * w1r.x, 0.f) * w2v.x;
                sum0 += fmaxf(acc[jt][1] + bs.y + wu0 * w1r.y, 0.f) * w2v.y;
                sum1 += fmaxf(acc[jt][2] + bs.x + wu1 * w1r.x, 0.f) * w2v.x;
                sum1 += fmaxf(acc[jt][3] + bs.y + wu1 * w1r.y, 0.f) * w2v.y;
            }
            sum0 += __shfl_xor_sync(0xffffffffu, sum0, 1);
            sum0 += __shfl_xor_sync(0xffffffffu, sum0, 2);
            sum1 += __shfl_xor_sync(0xffffffffu, sum1, 1);
            sum1 += __shfl_xor_sync(0xffffffffu, sum1, 2);
            if (tig == 0) {
                T->s_red[ngrp][mtile * 16 + gid]     = sum0;
                T->s_red[ngrp][mtile * 16 + gid + 8] = sum1;
            }
        }
    }
    __syncthreads();

    // ---- pi combine + mask (dtype-adaptive) ----
    float bb2 = b2[0];
    if (tid < U1N) {
        bool mv;
        if (g_mask_is_i32)
            mv = ((const int*)mask)[b * U1N + tid] != 0;
        else
            mv = ((const unsigned char*)mask)[b * U1N + tid] != 0;
        float pv = bb2 + T->s_red[0][tid] + T->s_red[1][tid];
        T->s_pi[tid] = mv ? -1000000.0f : pv;
    }
    __syncthreads();

    // ---- log_softmax + argmax (warp 0) ----
    if (wid == 0) {
        float mv = -3.4e38f; int mi = U1N;
        for (int u = lane; u < U1N; u += 32) {
            float v = T->s_pi[u];
            if (v > mv) { mv = v; mi = u; }
        }
        #pragma unroll
        for (int off = 16; off; off >>= 1) {
            float ov = __shfl_xor_sync(0xffffffffu, mv, off);
            int   oi = __shfl_xor_sync(0xffffffffu, mi, off);
            if (ov > mv || (ov == mv && oi < mi)) { mv = ov; mi = oi; }
        }
        float se = 0.f;
        for (int u = lane; u < U1N; u += 32) se += expf(T->s_pi[u] - mv);
        #pragma unroll
        for (int off = 16; off; off >>= 1)
            se += __shfl_xor_sync(0xffffffffu, se, off);
        if (lane == 0) { T->s_lse = mv + logf(se); T->s_sel_idx = mi; }
    }
    __syncthreads();

    float lse = T->s_lse;
    if (mode == 0) {
        for (int u = tid; u < U1N; u += 256)
            out[b * U1N + u] = T->s_pi[u] - lse;
    } else if (mode == 1) {
        if (tid == 0) out[b] = (float)T->s_sel_idx;
        float* op = out + BB;
        for (int u = tid; u < U1N; u += 256)
            op[b * U1N + u] = T->s_pi[u] - lse;
    } else {
        if (tid == 0) ((int*)out)[b] = T->s_sel_idx;
    }
}

// ---------------------------------------------------------------------------
extern "C" void kernel_launch(void* const* d_in, const int* in_sizes, int n_in,
                              void* d_out, int out_size)
{
    const float* emb  = (const float*)d_in[0];
    const float* w    = (const float*)d_in[1];
    const float* W_sc = (const float*)d_in[2];
    const float* b_sc = (const float*)d_in[3];
    const float* W1   = (const float*)d_in[4];
    const float* b1   = (const float*)d_in[5];
    const float* W2   = (const float*)d_in[6];
    const float* b2   = (const float*)d_in[7];
    const int*   seq  = (const int*)d_in[8];
    const void*  mask = d_in[9];

    int mode = 1;
    if (out_size == BB * U1N) mode = 0;
    else if (out_size == BB)  mode = 2;

    static int smem_sz = 0;
    if (!smem_sz) {
        smem_sz = OFF_TAIL + (int)sizeof(Tail);
        cudaFuncSetAttribute(fused_kernel,
                             cudaFuncAttributeMaxDynamicSharedMemorySize, smem_sz);
    }

    flag_init_kernel<<<1, 1>>>();
    mask_detect_kernel<<<208, 256>>>((const unsigned*)mask);
    bpack_kernel<<<(NT8 * KS * 32 + 255) / 256, 256>>>(W1);
    fused_kernel<<<BB, 256, smem_sz>>>(emb, w, W_sc, b_sc, W1, b1, W2, b2,
                                       seq, mask, (float*)d_out, mode);
}